// round 13
// baseline (speedup 1.0000x reference)
#include <cuda_runtime.h>
#include <cstdint>
#include <math.h>

#define Bb 64
#define Tt 512
#define Ff 256
#define Hh 512
#define TFs (Tt*Ff)
#define GRIDN 128
#define NTHR 512
#define WSTRIDE 772
#define WS_BYTES (24*WSTRIDE*4)        // 74112
// phase-1 slots (b-major layout)
#define VROWB 144
#define VSLOTB 9216
// phase-2 slots (kp layout): 16 kp-rows x 512B
#define VSLOTB2 8192
#define SMEM_BYTES (WS_BYTES + 16*VSLOTB)   // 221568 (phase-1 region governs)
#define OST (Tt*2*Hh)

typedef unsigned long long ull;

__device__ float g_h[2][2][Hh/2][Bb][2];   // [dir][slot][kpair][b][parity]
__device__ float g_xg[GRIDN][Tt][1536];    // precomputed x-gates (+bi), per block
__device__ ull   g_cnt[2][8][8];           // [dir][group][producer] monotonic

// ---------------- helpers ----------------
static __device__ __forceinline__ ull fma2(ull a, ull b, ull c) {
    ull d; asm("fma.rn.f32x2 %0, %1, %2, %3;" : "=l"(d) : "l"(a), "l"(b), "l"(c));
    return d;
}
static __device__ __forceinline__ float lof(ull x) { return __uint_as_float((unsigned)x); }
static __device__ __forceinline__ float hif(ull x) { return __uint_as_float((unsigned)(x >> 32)); }

// volatile is load-bearing (R5/R6 bug: pure asm hoists across barrier asms)
#define LDS128O(base, O, a, b) \
    asm volatile("ld.shared.v2.b64 {%0,%1}, [%2+" #O "];" : "=l"(a), "=l"(b) : "r"(base))
#define LDS64O(base, O, a) \
    asm volatile("ld.shared.b64 %0, [%1+" #O "];" : "=l"(a) : "r"(base))

static __device__ __forceinline__ void cpa16(unsigned s, const float4* g) {
    asm volatile("cp.async.cg.shared.global [%0], [%1], 16;"
                 :: "r"(s), "l"(__cvta_generic_to_global((const void*)g)));
}
static __device__ __forceinline__ void cpa_commit() {
    asm volatile("cp.async.commit_group;");
}
template<int N> static __device__ __forceinline__ void cpa_wait() {
    asm volatile("cp.async.wait_group %0;" :: "n"(N) : "memory");
}

static __device__ __forceinline__ float sigf(float x) {
    return __fdividef(1.f, 1.f + __expf(-x));
}
static __device__ __forceinline__ float tanf_fast(float x) {
    return __fdividef(2.f, 1.f + __expf(-2.f * x)) - 1.f;
}

static __device__ __forceinline__ void barp(int p) {
    asm volatile("bar.sync %0, 64;" :: "r"(p + 1) : "memory");
}

// producer publish: release store (preceded by all-thread fence + syncthreads)
static __device__ __forceinline__ void pubcnt(ull* addr, ull v) {
    asm volatile("st.release.gpu.global.u64 [%0], %1;" :: "l"(addr), "l"(v) : "memory");
}

// consumer wait: poll 8 counters (one 64B line) until min >= tgt, then acquire-fence
static __device__ __forceinline__ void wait_grp(const ull* g8, ull tgt) {
    while (true) {
        ull v0,v1,v2,v3,v4,v5,v6,v7;
        asm volatile("ld.volatile.global.v2.u64 {%0,%1}, [%2];" : "=l"(v0),"=l"(v1) : "l"(g8));
        asm volatile("ld.volatile.global.v2.u64 {%0,%1}, [%2];" : "=l"(v2),"=l"(v3) : "l"(g8+2));
        asm volatile("ld.volatile.global.v2.u64 {%0,%1}, [%2];" : "=l"(v4),"=l"(v5) : "l"(g8+4));
        asm volatile("ld.volatile.global.v2.u64 {%0,%1}, [%2];" : "=l"(v6),"=l"(v7) : "l"(g8+6));
        ull m = v0 < v1 ? v0 : v1;
        m = m < v2 ? m : v2;  m = m < v3 ? m : v3;
        m = m < v4 ? m : v4;  m = m < v5 ? m : v5;
        m = m < v6 ? m : v6;  m = m < v7 ? m : v7;
        if (m >= tgt) break;
        __nanosleep(20);
    }
    asm volatile("fence.acq_rel.gpu;" ::: "memory");
}

// phase-1 stage: 32k x 64b chunk, b-major rows (stride sstr), no commit
static __device__ __forceinline__ void stage32(unsigned dst, const float* sb,
                                               int sstr, int t2) {
#pragma unroll
    for (int j = 0; j < 8; ++j) {
        int idx = t2 + j * 64;
        int b = idx >> 3, f = idx & 7;
        cpa16(dst + (unsigned)(b * VROWB + f * 16),
              (const float4*)(sb + (size_t)b * sstr) + f);
    }
}
// phase-2 stage: contiguous 8KB copy, no commit
static __device__ __forceinline__ void stage32C(unsigned dst, const float* sb, int t2) {
#pragma unroll
    for (int j = 0; j < 8; ++j) {
        int idx = t2 + j * 64;
        cpa16(dst + (unsigned)idx * 16u, (const float4*)sb + idx);
    }
}

// shared fma body (48 fma.f32x2)
#define FMABODY \
  R0=fma2(a0,qa0,R0); R0=fma2(a1,qa1,R0); \
  R1=fma2(e0,qa0,R1); R1=fma2(e1,qa1,R1); \
  R2=fma2(f0,qa0,R2); R2=fma2(f1,qa1,R2); \
  R3=fma2(g0,qa0,R3); R3=fma2(g1,qa1,R3); \
  R4=fma2(a0,qb0,R4); R4=fma2(a1,qb1,R4); \
  R5=fma2(e0,qb0,R5); R5=fma2(e1,qb1,R5); \
  R6=fma2(f0,qb0,R6); R6=fma2(f1,qb1,R6); \
  R7=fma2(g0,qb0,R7); R7=fma2(g1,qb1,R7); \
  Z0=fma2(a0,sa0,Z0); Z0=fma2(a1,sa1,Z0); \
  Z1=fma2(e0,sa0,Z1); Z1=fma2(e1,sa1,Z1); \
  Z2=fma2(f0,sa0,Z2); Z2=fma2(f1,sa1,Z2); \
  Z3=fma2(g0,sa0,Z3); Z3=fma2(g1,sa1,Z3); \
  Z4=fma2(a0,sb0,Z4); Z4=fma2(a1,sb1,Z4); \
  Z5=fma2(e0,sb0,Z5); Z5=fma2(e1,sb1,Z5); \
  Z6=fma2(f0,sb0,Z6); Z6=fma2(f1,sb1,Z6); \
  Z7=fma2(g0,sb0,Z7); Z7=fma2(g1,sb1,Z7); \
  N0=fma2(a0,wa0,N0); N0=fma2(a1,wa1,N0); \
  N1=fma2(e0,wa0,N1); N1=fma2(e1,wa1,N1); \
  N2=fma2(f0,wa0,N2); N2=fma2(f1,wa1,N2); \
  N3=fma2(g0,wa0,N3); N3=fma2(g1,wa1,N3); \
  N4=fma2(a0,wb0,N4); N4=fma2(a1,wb1,N4); \
  N5=fma2(e0,wb0,N5); N5=fma2(e1,wb1,N5); \
  N6=fma2(f0,wb0,N6); N6=fma2(f1,wb1,N6); \
  N7=fma2(g0,wb0,N7); N7=fma2(g1,wb1,N7);

// phase-1 GITER (b-major v layout): 10 LDS.128
#define GITER(O) { \
  ull a0,a1,e0,e1,f0,f1,g0,g1; \
  ull qa0,qa1,qb0,qb1, sa0,sa1,sb0,sb1, wa0,wa1,wb0,wb1; \
  LDS128O(va0,O,a0,a1); LDS128O(va1,O,e0,e1); \
  LDS128O(va2,O,f0,f1); LDS128O(va3,O,g0,g1); \
  LDS128O(xr0,O,qa0,qa1); LDS128O(xr1,O,qb0,qb1); \
  LDS128O(xz0,O,sa0,sa1); LDS128O(xz1,O,sb0,sb1); \
  LDS128O(xn0,O,wa0,wa1); LDS128O(xn1,O,wb0,wb1); \
  FMABODY }

#define COMPUTE_CHUNK(SLOT, KK) { \
  const unsigned va0 = (SLOT) + vb0, va1 = (SLOT) + vb1, \
                 va2 = (SLOT) + vb2, va3 = (SLOT) + vb3; \
  const unsigned xr0 = wr0 + (unsigned)(KK)*4u, xr1 = wr1 + (unsigned)(KK)*4u; \
  const unsigned xz0 = wz0 + (unsigned)(KK)*4u, xz1 = wz1 + (unsigned)(KK)*4u; \
  const unsigned xn0 = wn0 + (unsigned)(KK)*4u, xn1 = wn1 + (unsigned)(KK)*4u; \
  GITER(0)  GITER(16) GITER(32) GITER(48) \
  GITER(64) GITER(80) GITER(96) GITER(112) }

// phase-2 GITER (kp-major v layout): 8 LDS.64 (1 wf each) + 6 LDS.128 (broadcast)
#define GITER2(OV0, OV1, OW) { \
  ull a0,a1,e0,e1,f0,f1,g0,g1; \
  ull qa0,qa1,qb0,qb1, sa0,sa1,sb0,sb1, wa0,wa1,wb0,wb1; \
  LDS64O(ua0,OV0,a0); LDS64O(ua0,OV1,a1); \
  LDS64O(ua1,OV0,e0); LDS64O(ua1,OV1,e1); \
  LDS64O(ua2,OV0,f0); LDS64O(ua2,OV1,f1); \
  LDS64O(ua3,OV0,g0); LDS64O(ua3,OV1,g1); \
  LDS128O(xr0,OW,qa0,qa1); LDS128O(xr1,OW,qb0,qb1); \
  LDS128O(xz0,OW,sa0,sa1); LDS128O(xz1,OW,sb0,sb1); \
  LDS128O(xn0,OW,wa0,wa1); LDS128O(xn1,OW,wb0,wb1); \
  FMABODY }

#define COMPUTE_CHUNK2(SLOT, KK) { \
  const unsigned ua0 = (SLOT) + (unsigned)(bb*8), ua1 = ua0 + 128u, \
                 ua2 = ua0 + 256u, ua3 = ua0 + 384u; \
  const unsigned xr0 = wr0 + (unsigned)(KK)*4u, xr1 = wr1 + (unsigned)(KK)*4u; \
  const unsigned xz0 = wz0 + (unsigned)(KK)*4u, xz1 = wz1 + (unsigned)(KK)*4u; \
  const unsigned xn0 = wn0 + (unsigned)(KK)*4u, xn1 = wn1 + (unsigned)(KK)*4u; \
  GITER2(0,512,0)       GITER2(1024,1536,16) \
  GITER2(2048,2560,32)  GITER2(3072,3584,48) \
  GITER2(4096,4608,64)  GITER2(5120,5632,80) \
  GITER2(6144,6656,96)  GITER2(7168,7680,112) }

#define P1ST(ACC, GA, CG, G, BI) \
  xgrow[((GA)*8 + cg4 + 4*(CG))*64 + bb + 16*(G)] = lof(ACC) + hif(ACC) + (BI);

#define PUB(GA, M, ACC) rp[(GA)*512 + (M)*64 + t2] = lof(ACC) + hif(ACC);

// ---------------- persistent fused BiGRU ----------------
extern "C" __global__ void __launch_bounds__(NTHR, 1)
gru_persist(const float* __restrict__ data,
            const float* __restrict__ Wi_f, const float* __restrict__ bi_f,
            const float* __restrict__ Wh_f, const float* __restrict__ bhn_f,
            const float* __restrict__ Wi_b, const float* __restrict__ bi_b,
            const float* __restrict__ Wh_b, const float* __restrict__ bhn_b,
            float* __restrict__ out) {
    extern __shared__ float smem[];
    float* Ws   = smem;                                  // [24][772]
    float* redF = (float*)((char*)smem + WS_BYTES);      // overlays phase-2 slots
    __shared__ ull sBase;

    const int tid = threadIdx.x;
    const int bid = blockIdx.x;
    const int d   = bid >> 6;
    const int cb  = (bid & 63) * 8;
    const int grp  = (bid & 63) >> 3;   // my producer group
    const int gidx = bid & 7;           // my slot in the group

    const float* Wi  = d ? Wi_b  : Wi_f;
    const float* Wh  = d ? Wh_b  : Wh_f;
    const float* bi  = d ? bi_b  : bi_f;
    const float* bhn = d ? bhn_b : bhn_f;

    // read my own counter (monotonic; all counters equal at kernel entry)
    if (tid == 0) {
        ull v;
        asm volatile("ld.volatile.global.u64 %0, [%1];" : "=l"(v) : "l"(&g_cnt[d][grp][gidx]));
        sBase = v;
    }

    for (int idx = tid; idx < 24 * 768; idx += NTHR) {
        int k = idx / 24, j = idx - k * 24;
        int g = j >> 3, cc = j & 7;
        int gcol = g * Hh + cb + cc;
        Ws[j * WSTRIDE + k] = (k < Ff) ? Wi[(size_t)k * (3 * Hh) + gcol]
                                       : Wh[(size_t)(k - Ff) * (3 * Hh) + gcol];
    }
    // zero my 8 h-columns of slot 0 (contiguous 512 floats in kp layout)
    ((float*)&g_h[d][0][cb >> 1][0][0])[tid] = 0.f;

    __threadfence();
    __syncthreads();
    const ull base = sBase;
    if (tid == 0) pubcnt(&g_cnt[d][grp][gidx], base + 1);   // h_in(0) ready

    const int p   = tid >> 6;
    const int t2  = tid & 63;
    const int bb  = t2 & 15;
    const int cg4 = t2 >> 4;

    // epilogue cell mapping (cell m = tid)
    const int eM  = tid >> 6, et2 = tid & 63;
    const int ebq = (et2 & 15) + 16 * (eM & 3);
    const int ecc = (et2 >> 4) + 4 * (eM >> 2);
    const float ebh = bhn[cb + ecc];

    const float bi00 = bi[cb + cg4],        bi01 = bi[cb + cg4 + 4];
    const float bi10 = bi[Hh + cb + cg4],   bi11 = bi[Hh + cb + cg4 + 4];
    const float bi20 = bi[2*Hh + cb + cg4], bi21 = bi[2*Hh + cb + cg4 + 4];

    const unsigned wsA = (unsigned)__cvta_generic_to_shared(Ws);
    const unsigned vsA = (unsigned)__cvta_generic_to_shared((char*)smem + WS_BYTES);
    const unsigned xgA = vsA + 131072u;
    const unsigned vb0 = (unsigned)(bb        * VROWB);
    const unsigned vb1 = (unsigned)((bb + 16) * VROWB);
    const unsigned vb2 = (unsigned)((bb + 32) * VROWB);
    const unsigned vb3 = (unsigned)((bb + 48) * VROWB);
    const unsigned wr0 = wsA + (unsigned)((0  + cg4)     * WSTRIDE) * 4u;
    const unsigned wr1 = wsA + (unsigned)((0  + cg4 + 4) * WSTRIDE) * 4u;
    const unsigned wz0 = wsA + (unsigned)((8  + cg4)     * WSTRIDE) * 4u;
    const unsigned wz1 = wsA + (unsigned)((8  + cg4 + 4) * WSTRIDE) * 4u;
    const unsigned wn0 = wsA + (unsigned)((16 + cg4)     * WSTRIDE) * 4u;
    const unsigned wn1 = wsA + (unsigned)((16 + cg4 + 4) * WSTRIDE) * 4u;

    // ===== PHASE 1: xg = x@Wi + bi (own block only; partition p owns t = 8j+p) =====
    {
        const unsigned SA = vsA + (unsigned)(2 * p)     * VSLOTB;
        const unsigned SB = vsA + (unsigned)(2 * p + 1) * VSLOTB;
        stage32(SA, data + (size_t)p * Ff,      TFs, t2); cpa_commit();
        stage32(SB, data + (size_t)p * Ff + 32, TFs, t2); cpa_commit();

        for (int jt = 0; jt < 64; ++jt) {
            const int t = 8 * jt + p;
            ull R0=0,R1=0,R2=0,R3=0,R4=0,R5=0,R6=0,R7=0;
            ull Z0=0,Z1=0,Z2=0,Z3=0,Z4=0,Z5=0,Z6=0,Z7=0;
            ull N0=0,N1=0,N2=0,N3=0,N4=0,N5=0,N6=0,N7=0;

            #pragma unroll 1
            for (int j = 0; j < 8; ++j) {
                if (jt == 63 && j == 7) { cpa_wait<0>(); } else { cpa_wait<1>(); }
                barp(p);
                COMPUTE_CHUNK((j & 1) ? SB : SA, 32 * j);
                barp(p);
                if (jt < 63 || j < 6) {
                    const int tS = (j < 6) ? t : t + 8;
                    const int kS = ((j + 2) & 7) * 32;
                    stage32((j & 1) ? SB : SA, data + (size_t)tS * Ff + kS, TFs, t2);
                    cpa_commit();
                }
            }

            float* xgrow = &g_xg[bid][t][0];
            P1ST(R0,0,0,0,bi00) P1ST(R1,0,0,1,bi00) P1ST(R2,0,0,2,bi00) P1ST(R3,0,0,3,bi00)
            P1ST(R4,0,1,0,bi01) P1ST(R5,0,1,1,bi01) P1ST(R6,0,1,2,bi01) P1ST(R7,0,1,3,bi01)
            P1ST(Z0,1,0,0,bi10) P1ST(Z1,1,0,1,bi10) P1ST(Z2,1,0,2,bi10) P1ST(Z3,1,0,3,bi10)
            P1ST(Z4,1,1,0,bi11) P1ST(Z5,1,1,1,bi11) P1ST(Z6,1,1,2,bi11) P1ST(Z7,1,1,3,bi11)
            P1ST(N0,2,0,0,bi20) P1ST(N1,2,0,1,bi20) P1ST(N2,2,0,2,bi20) P1ST(N3,2,0,3,bi20)
            P1ST(N4,2,1,0,bi21) P1ST(N5,2,1,1,bi21) P1ST(N6,2,1,2,bi21) P1ST(N7,2,1,3,bi21)
        }
    }

    // phase boundary: xg stores (own block) must be L2-visible for cp.async reads
    __threadfence();
    __syncthreads();

    // ===== PHASE 2: recurrence (kp-layout slots; partition p: 16KB at p*16384) =====
    const unsigned SA2 = vsA + (unsigned)p * 16384u;
    const unsigned SB2 = SA2 + (unsigned)VSLOTB2;
    const int K0h = p * 64;
    float hprev = 0.f;

    {   // initial stage for t=0 (slot 0): wait group p producers' zeros
        if (t2 == 0) wait_grp(&g_cnt[d][p][0], base + 1);
        barp(p);
        const float* hb = &g_h[d][0][0][0][0];
        stage32C(SA2, hb + K0h * 64, t2);
        if (p == 0) {
            const float4* xs = (const float4*)&g_xg[bid][0][0];
            #pragma unroll
            for (int i = 0; i < 6; ++i)
                cpa16(xgA + (unsigned)((t2 + i * 64) * 16), xs + t2 + i * 64);
        }
        cpa_commit();
        stage32C(SB2, hb + K0h * 64 + 2048, t2);
        cpa_commit();
    }

    for (int t = 0; t < Tt; ++t) {
        const int ws = (t + 1) & 1;

        ull R0=0,R1=0,R2=0,R3=0,R4=0,R5=0,R6=0,R7=0;
        ull Z0=0,Z1=0,Z2=0,Z3=0,Z4=0,Z5=0,Z6=0,Z7=0;
        ull N0=0,N1=0,N2=0,N3=0,N4=0,N5=0,N6=0,N7=0;

        cpa_wait<1>(); barp(p);
        COMPUTE_CHUNK2(SA2, 256 + K0h);
        cpa_wait<0>(); barp(p);
        COMPUTE_CHUNK2(SB2, 256 + K0h + 32);
        barp(p);   // partition done reading its slots (+compiler fence)

        {   // publish f32 partials into OWN slot region (16KB stride)
            float* rp = redF + (size_t)p * 4096;
            PUB(0,0,R0) PUB(0,1,R1) PUB(0,2,R2) PUB(0,3,R3)
            PUB(0,4,R4) PUB(0,5,R5) PUB(0,6,R6) PUB(0,7,R7)
            PUB(1,0,Z0) PUB(1,1,Z1) PUB(1,2,Z2) PUB(1,3,Z3)
            PUB(1,4,Z4) PUB(1,5,Z5) PUB(1,6,Z6) PUB(1,7,Z7)
            PUB(2,0,N0) PUB(2,1,N1) PUB(2,2,N2) PUB(2,3,N3)
            PUB(2,4,N4) PUB(2,5,N5) PUB(2,6,N6) PUB(2,7,N7)
        }
        __syncthreads();

        {   // distributed epilogue: thread finalizes cell m = tid (hprev in reg)
            float Rm = 0.f, Zm = 0.f, Nm = 0.f;
            #pragma unroll
            for (int q = 0; q < 8; ++q) {
                const float* e = redF + (size_t)q * 4096;
                Rm += e[tid]; Zm += e[512 + tid]; Nm += e[1024 + tid];
            }
            const float* xgS = (const float*)((char*)smem + WS_BYTES + 131072);
            float xr = xgS[(0*8 + ecc) * 64 + ebq];
            float xz = xgS[(1*8 + ecc) * 64 + ebq];
            float xn = xgS[(2*8 + ecc) * 64 + ebq];
            float rv = sigf(xr + Rm);
            float zv = sigf(xz + Zm);
            float nv = tanf_fast(xn + rv * (Nm + ebh));
            float hnew = (1.f - zv) * nv + zv * hprev;
            hprev = hnew;
            g_h[d][ws][(cb + ecc) >> 1][ebq][ecc & 1] = hnew;
            out[(size_t)ebq * OST + (size_t)t * (2 * Hh) + (size_t)d * Hh + cb + ecc] = hnew;
        }

        __threadfence();
        __syncthreads();
        if (tid == 0) pubcnt(&g_cnt[d][grp][gidx], base + t + 2);   // h_in(t+1) ready

        if (t + 1 < Tt) {
            if (t2 == 0) wait_grp(&g_cnt[d][p][0], base + t + 2);
            barp(p);
            const float* hb = &g_h[d][ws][0][0][0];
            stage32C(SA2, hb + K0h * 64, t2);
            if (p == 0) {
                const float4* xs = (const float4*)&g_xg[bid][t + 1][0];
                #pragma unroll
                for (int i = 0; i < 6; ++i)
                    cpa16(xgA + (unsigned)((t2 + i * 64) * 16), xs + t2 + i * 64);
            }
            cpa_commit();
            stage32C(SB2, hb + K0h * 64 + 2048, t2);
            cpa_commit();
        }
    }
}

extern "C" void kernel_launch(void* const* d_in, const int* in_sizes, int n_in,
                              void* d_out, int out_size) {
    const float* data  = (const float*)d_in[0];
    const float* Wi_f  = (const float*)d_in[1];
    const float* bi_f  = (const float*)d_in[2];
    const float* Wh_f  = (const float*)d_in[3];
    const float* bhn_f = (const float*)d_in[4];
    const float* Wi_b  = (const float*)d_in[5];
    const float* bi_b  = (const float*)d_in[6];
    const float* Wh_b  = (const float*)d_in[7];
    const float* bhn_b = (const float*)d_in[8];
    float* out = (float*)d_out;

    cudaFuncSetAttribute(gru_persist, cudaFuncAttributeMaxDynamicSharedMemorySize, SMEM_BYTES);

    gru_persist<<<GRIDN, NTHR, SMEM_BYTES>>>(data, Wi_f, bi_f, Wh_f, bhn_f,
                                             Wi_b, bi_b, Wh_b, bhn_b, out);
}

// round 14
// speedup vs baseline: 1.2644x; 1.2644x over previous
#include <cuda_runtime.h>
#include <cstdint>
#include <math.h>

#define Bb 64
#define Tt 512
#define Ff 256
#define Hh 512
#define TFs (Tt*Ff)
#define GRIDN 128
#define NTHR 512
#define WSTRIDE 772
#define WS_BYTES (24*WSTRIDE*4)        // 74112
// phase-1 slots (b-major layout)
#define VROWB 144
#define VSLOTB 9216
// phase-2 slots (kp layout): 16 kp-rows x 512B
#define VSLOTB2 8192
#define SMEM_BYTES (WS_BYTES + 16*VSLOTB)   // 221568 (phase-1 layout governs)
#define OST (Tt*2*Hh)
// red layout: dir*7680 + p*960 + gate*320 + m*80 + t2   (floats)
#define REDD 7680

typedef unsigned long long ull;

__device__ float g_h[2][2][Hh/2][Bb][2];   // [dir][slot][kpair][b][parity]
__device__ float g_xg[GRIDN][Tt][1536];    // precomputed x-gates (+bi), per block
__device__ ull   g_cnt[2][16];             // per-dir monotonic arrival counters

// ---------------- helpers ----------------
static __device__ __forceinline__ ull fma2(ull a, ull b, ull c) {
    ull d; asm("fma.rn.f32x2 %0, %1, %2, %3;" : "=l"(d) : "l"(a), "l"(b), "l"(c));
    return d;
}
static __device__ __forceinline__ float lof(ull x) { return __uint_as_float((unsigned)x); }
static __device__ __forceinline__ float hif(ull x) { return __uint_as_float((unsigned)(x >> 32)); }

// volatile is load-bearing (R5/R6 bug: pure asm hoists across barrier asms)
#define LDS128O(base, O, a, b) \
    asm volatile("ld.shared.v2.b64 {%0,%1}, [%2+" #O "];" : "=l"(a), "=l"(b) : "r"(base))
#define LDS64O(base, O, a) \
    asm volatile("ld.shared.b64 %0, [%1+" #O "];" : "=l"(a) : "r"(base))

static __device__ __forceinline__ void cpa16(unsigned s, const float4* g) {
    asm volatile("cp.async.cg.shared.global [%0], [%1], 16;"
                 :: "r"(s), "l"(__cvta_generic_to_global((const void*)g)));
}
static __device__ __forceinline__ void cpa_commit() {
    asm volatile("cp.async.commit_group;");
}
template<int N> static __device__ __forceinline__ void cpa_wait() {
    asm volatile("cp.async.wait_group %0;" :: "n"(N) : "memory");
}

static __device__ __forceinline__ float sigf(float x) {
    return __fdividef(1.f, 1.f + __expf(-x));
}
static __device__ __forceinline__ float tanf_fast(float x) {
    return __fdividef(2.f, 1.f + __expf(-2.f * x)) - 1.f;
}

static __device__ __forceinline__ void barp(int p) {
    asm volatile("bar.sync %0, 64;" :: "r"(p + 1) : "memory");
}

// split arrive/poll barrier on a monotonic counter (graph-replay safe)
static __device__ __forceinline__ ull arrive_cnt(ull* ctr) {
    ull old;
    asm volatile("atom.release.gpu.global.add.u64 %0, [%1], 1;"
                 : "=l"(old) : "l"(ctr) : "memory");
    return (old / (ull)GRIDN + 1ULL) * (ull)GRIDN;
}
static __device__ __forceinline__ void poll_cnt(ull* ctr, ull tgt) {
    while (true) {
        ull cur;
        asm volatile("ld.acquire.gpu.global.u64 %0, [%1];"
                     : "=l"(cur) : "l"(ctr) : "memory");
        if (cur >= tgt) break;
        __nanosleep(20);
    }
}

// phase-1 stage: 32k x 64b chunk, b-major rows (stride sstr), no commit
static __device__ __forceinline__ void stage32(unsigned dst, const float* sb,
                                               int sstr, int t2) {
#pragma unroll
    for (int j = 0; j < 8; ++j) {
        int idx = t2 + j * 64;
        int b = idx >> 3, f = idx & 7;
        cpa16(dst + (unsigned)(b * VROWB + f * 16),
              (const float4*)(sb + (size_t)b * sstr) + f);
    }
}
// phase-2 stage: contiguous 8KB copy, no commit
static __device__ __forceinline__ void stage32C(unsigned dst, const float* sb, int t2) {
#pragma unroll
    for (int j = 0; j < 8; ++j) {
        int idx = t2 + j * 64;
        cpa16(dst + (unsigned)idx * 16u, (const float4*)sb + idx);
    }
}

// ---- phase-1 machinery (unchanged from R12; rows remapped semantically) ----
#define FMABODY \
  R0=fma2(a0,qa0,R0); R0=fma2(a1,qa1,R0); \
  R1=fma2(e0,qa0,R1); R1=fma2(e1,qa1,R1); \
  R2=fma2(f0,qa0,R2); R2=fma2(f1,qa1,R2); \
  R3=fma2(g0,qa0,R3); R3=fma2(g1,qa1,R3); \
  R4=fma2(a0,qb0,R4); R4=fma2(a1,qb1,R4); \
  R5=fma2(e0,qb0,R5); R5=fma2(e1,qb1,R5); \
  R6=fma2(f0,qb0,R6); R6=fma2(f1,qb1,R6); \
  R7=fma2(g0,qb0,R7); R7=fma2(g1,qb1,R7); \
  Z0=fma2(a0,sa0,Z0); Z0=fma2(a1,sa1,Z0); \
  Z1=fma2(e0,sa0,Z1); Z1=fma2(e1,sa1,Z1); \
  Z2=fma2(f0,sa0,Z2); Z2=fma2(f1,sa1,Z2); \
  Z3=fma2(g0,sa0,Z3); Z3=fma2(g1,sa1,Z3); \
  Z4=fma2(a0,sb0,Z4); Z4=fma2(a1,sb1,Z4); \
  Z5=fma2(e0,sb0,Z5); Z5=fma2(e1,sb1,Z5); \
  Z6=fma2(f0,sb0,Z6); Z6=fma2(f1,sb1,Z6); \
  Z7=fma2(g0,sb0,Z7); Z7=fma2(g1,sb1,Z7); \
  N0=fma2(a0,wa0,N0); N0=fma2(a1,wa1,N0); \
  N1=fma2(e0,wa0,N1); N1=fma2(e1,wa1,N1); \
  N2=fma2(f0,wa0,N2); N2=fma2(f1,wa1,N2); \
  N3=fma2(g0,wa0,N3); N3=fma2(g1,wa1,N3); \
  N4=fma2(a0,wb0,N4); N4=fma2(a1,wb1,N4); \
  N5=fma2(e0,wb0,N5); N5=fma2(e1,wb1,N5); \
  N6=fma2(f0,wb0,N6); N6=fma2(f1,wb1,N6); \
  N7=fma2(g0,wb0,N7); N7=fma2(g1,wb1,N7);

#define GITER(O) { \
  ull a0,a1,e0,e1,f0,f1,g0,g1; \
  ull qa0,qa1,qb0,qb1, sa0,sa1,sb0,sb1, wa0,wa1,wb0,wb1; \
  LDS128O(va0,O,a0,a1); LDS128O(va1,O,e0,e1); \
  LDS128O(va2,O,f0,f1); LDS128O(va3,O,g0,g1); \
  LDS128O(xr0,O,qa0,qa1); LDS128O(xr1,O,qb0,qb1); \
  LDS128O(xz0,O,sa0,sa1); LDS128O(xz1,O,sb0,sb1); \
  LDS128O(xn0,O,wa0,wa1); LDS128O(xn1,O,wb0,wb1); \
  FMABODY }

#define COMPUTE_CHUNK(SLOT, KK) { \
  const unsigned va0 = (SLOT) + vb0, va1 = (SLOT) + vb1, \
                 va2 = (SLOT) + vb2, va3 = (SLOT) + vb3; \
  const unsigned xr0 = wr0 + (unsigned)(KK)*4u, xr1 = wr1 + (unsigned)(KK)*4u; \
  const unsigned xz0 = wz0 + (unsigned)(KK)*4u, xz1 = wz1 + (unsigned)(KK)*4u; \
  const unsigned xn0 = wn0 + (unsigned)(KK)*4u, xn1 = wn1 + (unsigned)(KK)*4u; \
  GITER(0)  GITER(16) GITER(32) GITER(48) \
  GITER(64) GITER(80) GITER(96) GITER(112) }

// ---- phase-2 machinery: 4b x 1c per dir ----
#define GITER2D(OV0, OV1, OW, WRX, WZX, WNX, A0,A1,A2,A3, B0,B1,B2,B3, C0,C1,C2,C3) { \
  ull a0,a1,e0,e1,f0,f1,g0,g1, q0,q1, s0,s1, w0,w1; \
  LDS64O(ua0,OV0,a0); LDS64O(ua0,OV1,a1); \
  LDS64O(ua1,OV0,e0); LDS64O(ua1,OV1,e1); \
  LDS64O(ua2,OV0,f0); LDS64O(ua2,OV1,f1); \
  LDS64O(ua3,OV0,g0); LDS64O(ua3,OV1,g1); \
  LDS128O(WRX,OW,q0,q1); LDS128O(WZX,OW,s0,s1); LDS128O(WNX,OW,w0,w1); \
  A0=fma2(a0,q0,A0); A0=fma2(a1,q1,A0); \
  A1=fma2(e0,q0,A1); A1=fma2(e1,q1,A1); \
  A2=fma2(f0,q0,A2); A2=fma2(f1,q1,A2); \
  A3=fma2(g0,q0,A3); A3=fma2(g1,q1,A3); \
  B0=fma2(a0,s0,B0); B0=fma2(a1,s1,B0); \
  B1=fma2(e0,s0,B1); B1=fma2(e1,s1,B1); \
  B2=fma2(f0,s0,B2); B2=fma2(f1,s1,B2); \
  B3=fma2(g0,s0,B3); B3=fma2(g1,s1,B3); \
  C0=fma2(a0,w0,C0); C0=fma2(a1,w1,C0); \
  C1=fma2(e0,w0,C1); C1=fma2(e1,w1,C1); \
  C2=fma2(f0,w0,C2); C2=fma2(f1,w1,C2); \
  C3=fma2(g0,w0,C3); C3=fma2(g1,w1,C3); }

#define CCHUNK(SLOT, KK, WRX, WZX, WNX, A0,A1,A2,A3, B0,B1,B2,B3, C0,C1,C2,C3) { \
  const unsigned ua0 = (SLOT) + (unsigned)(bb*8), ua1 = ua0 + 128u, \
                 ua2 = ua0 + 256u, ua3 = ua0 + 384u; \
  const unsigned wR = (WRX) + (unsigned)(KK)*4u; \
  const unsigned wZ = (WZX) + (unsigned)(KK)*4u; \
  const unsigned wN = (WNX) + (unsigned)(KK)*4u; \
  GITER2D(0,512,0,       wR,wZ,wN, A0,A1,A2,A3, B0,B1,B2,B3, C0,C1,C2,C3) \
  GITER2D(1024,1536,16,  wR,wZ,wN, A0,A1,A2,A3, B0,B1,B2,B3, C0,C1,C2,C3) \
  GITER2D(2048,2560,32,  wR,wZ,wN, A0,A1,A2,A3, B0,B1,B2,B3, C0,C1,C2,C3) \
  GITER2D(3072,3584,48,  wR,wZ,wN, A0,A1,A2,A3, B0,B1,B2,B3, C0,C1,C2,C3) \
  GITER2D(4096,4608,64,  wR,wZ,wN, A0,A1,A2,A3, B0,B1,B2,B3, C0,C1,C2,C3) \
  GITER2D(5120,5632,80,  wR,wZ,wN, A0,A1,A2,A3, B0,B1,B2,B3, C0,C1,C2,C3) \
  GITER2D(6144,6656,96,  wR,wZ,wN, A0,A1,A2,A3, B0,B1,B2,B3, C0,C1,C2,C3) \
  GITER2D(7168,7680,112, wR,wZ,wN, A0,A1,A2,A3, B0,B1,B2,B3, C0,C1,C2,C3) }

// phase-1 store: row = GA*8 + cg4 + 4*CG  (GA=gate, CG=dir, cg4=col)
#define P1ST(ACC, GA, CG, G, BI) \
  xgrow[((GA)*8 + cg4 + 4*(CG))*64 + bb + 16*(G)] = lof(ACC) + hif(ACC) + (BI);

// publish one partial (f32): red[dir*7680 + p*960 + g*320 + m*80 + t2]
#define PUB(DIR, G, M, ACC) \
  redF[(DIR)*REDD + (size_t)p*960 + (G)*320 + (M)*80 + t2] = lof(ACC) + hif(ACC);

// ---------------- persistent fused BiGRU (both dirs per block) ----------------
extern "C" __global__ void __launch_bounds__(NTHR, 1)
gru_persist(const float* __restrict__ data,
            const float* __restrict__ Wi_f, const float* __restrict__ bi_f,
            const float* __restrict__ Wh_f, const float* __restrict__ bhn_f,
            const float* __restrict__ Wi_b, const float* __restrict__ bi_b,
            const float* __restrict__ Wh_b, const float* __restrict__ bhn_b,
            float* __restrict__ out) {
    extern __shared__ float smem[];
    float* Ws   = smem;                                  // [24][772]
    float* redF = (float*)((char*)smem + WS_BYTES);      // overlays phase-2 slots

    const int tid = threadIdx.x;
    const int bid = blockIdx.x;
    const int cb4 = bid * 4;                 // column base, both directions

    // stage fused weights once: row j -> dir=(j>>2)&1, gate=j>>3, col=j&3
    for (int idx = tid; idx < 24 * 768; idx += NTHR) {
        int k = idx / 24, j = idx - k * 24;
        int dd = (j >> 2) & 1, g = j >> 3, cc = j & 3;
        int gcol = g * Hh + cb4 + cc;
        const float* WiD = dd ? Wi_b : Wi_f;
        const float* WhD = dd ? Wh_b : Wh_f;
        Ws[j * WSTRIDE + k] = (k < Ff) ? WiD[(size_t)k * (3 * Hh) + gcol]
                                       : WhD[(size_t)(k - Ff) * (3 * Hh) + gcol];
    }
    // zero slot-0 h for my 4 cols x both dirs (512 cells, 1 per thread)
    {
        int dd = tid >> 8, rem = tid & 255;
        int col = cb4 + (rem >> 6), b = rem & 63;
        g_h[dd][0][col >> 1][b][col & 1] = 0.f;
    }
    __threadfence();
    __syncthreads();
    ull tgtI0 = 0, tgtI1 = 0;
    if (tid == 0) {
        tgtI0 = arrive_cnt(&g_cnt[0][0]);
        tgtI1 = arrive_cnt(&g_cnt[1][0]);
    }

    const int p   = tid >> 6;
    const int t2  = tid & 63;
    const int bb  = t2 & 15;
    const int cg4 = t2 >> 4;

    // epilogue cell mapping: thread = cell (dir, col, b)
    const int edir = tid >> 8;
    const int erem = tid & 255;
    const int ec   = erem >> 6;      // col within block
    const int eb   = erem & 63;
    const int ecol = cb4 + ec;
    const float ebh = (edir ? bhn_b : bhn_f)[ecol];
    float* hOut = &g_h[edir][0][ecol >> 1][eb][ecol & 1];   // + ws*32768
    const size_t outBase = (size_t)eb * OST + (size_t)edir * Hh + ecol;

    // phase-1 biases: CG = dir
    const float bi00 = bi_f[cb4 + cg4],          bi01 = bi_b[cb4 + cg4];
    const float bi10 = bi_f[Hh + cb4 + cg4],     bi11 = bi_b[Hh + cb4 + cg4];
    const float bi20 = bi_f[2*Hh + cb4 + cg4],   bi21 = bi_b[2*Hh + cb4 + cg4];

    const unsigned wsA = (unsigned)__cvta_generic_to_shared(Ws);
    const unsigned vsA = (unsigned)__cvta_generic_to_shared((char*)smem + WS_BYTES);
    const unsigned xgA = vsA + 131072u;
    const unsigned vb0 = (unsigned)(bb        * VROWB);
    const unsigned vb1 = (unsigned)((bb + 16) * VROWB);
    const unsigned vb2 = (unsigned)((bb + 32) * VROWB);
    const unsigned vb3 = (unsigned)((bb + 48) * VROWB);
    // weight row bases: wr0 = (d0, gate0, col cg4), wr1 = (d1, gate0, col cg4), ...
    const unsigned wr0 = wsA + (unsigned)((0  + cg4)     * WSTRIDE) * 4u;
    const unsigned wr1 = wsA + (unsigned)((0  + cg4 + 4) * WSTRIDE) * 4u;
    const unsigned wz0 = wsA + (unsigned)((8  + cg4)     * WSTRIDE) * 4u;
    const unsigned wz1 = wsA + (unsigned)((8  + cg4 + 4) * WSTRIDE) * 4u;
    const unsigned wn0 = wsA + (unsigned)((16 + cg4)     * WSTRIDE) * 4u;
    const unsigned wn1 = wsA + (unsigned)((16 + cg4 + 4) * WSTRIDE) * 4u;

    // ===== PHASE 1: xg = x@Wi + bi, 24 rows (both dirs), partition p owns t=8j+p =====
    {
        const unsigned SA = vsA + (unsigned)(2 * p)     * VSLOTB;
        const unsigned SB = vsA + (unsigned)(2 * p + 1) * VSLOTB;
        stage32(SA, data + (size_t)p * Ff,      TFs, t2); cpa_commit();
        stage32(SB, data + (size_t)p * Ff + 32, TFs, t2); cpa_commit();

        for (int jt = 0; jt < 64; ++jt) {
            const int t = 8 * jt + p;
            ull R0=0,R1=0,R2=0,R3=0,R4=0,R5=0,R6=0,R7=0;
            ull Z0=0,Z1=0,Z2=0,Z3=0,Z4=0,Z5=0,Z6=0,Z7=0;
            ull N0=0,N1=0,N2=0,N3=0,N4=0,N5=0,N6=0,N7=0;

            #pragma unroll 1
            for (int j = 0; j < 8; ++j) {
                if (jt == 63 && j == 7) { cpa_wait<0>(); } else { cpa_wait<1>(); }
                barp(p);
                COMPUTE_CHUNK((j & 1) ? SB : SA, 32 * j);
                barp(p);
                if (jt < 63 || j < 6) {
                    const int tS = (j < 6) ? t : t + 8;
                    const int kS = ((j + 2) & 7) * 32;
                    stage32((j & 1) ? SB : SA, data + (size_t)tS * Ff + kS, TFs, t2);
                    cpa_commit();
                }
            }

            float* xgrow = &g_xg[bid][t][0];
            P1ST(R0,0,0,0,bi00) P1ST(R1,0,0,1,bi00) P1ST(R2,0,0,2,bi00) P1ST(R3,0,0,3,bi00)
            P1ST(R4,0,1,0,bi01) P1ST(R5,0,1,1,bi01) P1ST(R6,0,1,2,bi01) P1ST(R7,0,1,3,bi01)
            P1ST(Z0,1,0,0,bi10) P1ST(Z1,1,0,1,bi10) P1ST(Z2,1,0,2,bi10) P1ST(Z3,1,0,3,bi10)
            P1ST(Z4,1,1,0,bi11) P1ST(Z5,1,1,1,bi11) P1ST(Z6,1,1,2,bi11) P1ST(Z7,1,1,3,bi11)
            P1ST(N0,2,0,0,bi20) P1ST(N1,2,0,1,bi20) P1ST(N2,2,0,2,bi20) P1ST(N3,2,0,3,bi20)
            P1ST(N4,2,1,0,bi21) P1ST(N5,2,1,1,bi21) P1ST(N6,2,1,2,bi21) P1ST(N7,2,1,3,bi21)
        }
    }

    // xg visibility for cp.async; then wait everyone's h zeros
    __threadfence();
    __syncthreads();
    if (tid == 0) {
        poll_cnt(&g_cnt[0][0], tgtI0);
        poll_cnt(&g_cnt[1][0], tgtI1);
        asm volatile("fence.acq_rel.gpu;" ::: "memory");
    }
    __syncthreads();

    // ===== PHASE 2 =====
    const unsigned SA2 = vsA + (unsigned)p * 16384u;
    const unsigned SB2 = SA2 + (unsigned)VSLOTB2;
    const int K0h = p * 64;
    float hprev = 0.f;

    {   // initial stage for t=0: d0 h halves (+ xg(0) bundled with first group)
        const float* hb0 = &g_h[0][0][0][0][0];
        stage32C(SA2, hb0 + K0h * 64, t2);
        if (p == 0) {
            const float4* xs = (const float4*)&g_xg[bid][0][0];
            #pragma unroll
            for (int i = 0; i < 6; ++i)
                cpa16(xgA + (unsigned)((t2 + i * 64) * 16), xs + t2 + i * 64);
        }
        cpa_commit();
        stage32C(SB2, hb0 + K0h * 64 + 2048, t2);
        cpa_commit();
    }

    for (int t = 0; t < Tt; ++t) {
        const int rs = t & 1;
        const int ws = rs ^ 1;
        const float* hb1 = &g_h[1][rs][0][0][0];

        ull R0=0,R1=0,R2=0,R3=0, Z0=0,Z1=0,Z2=0,Z3=0, N0=0,N1=0,N2=0,N3=0;   // d0
        ull S0=0,S1=0,S2=0,S3=0, Y0=0,Y1=0,Y2=0,Y3=0, M0=0,M1=0,M2=0,M3=0;   // d1

        // d0 chunk A, then refill A with d1 h (available since prev step)
        cpa_wait<1>(); barp(p);
        CCHUNK(SA2, 256 + K0h, wr0, wz0, wn0, R0,R1,R2,R3, Z0,Z1,Z2,Z3, N0,N1,N2,N3);
        barp(p);
        stage32C(SA2, hb1 + K0h * 64, t2); cpa_commit();

        // d0 chunk B, refill B with d1 h
        cpa_wait<1>(); barp(p);
        CCHUNK(SB2, 256 + K0h + 32, wr0, wz0, wn0, R0,R1,R2,R3, Z0,Z1,Z2,Z3, N0,N1,N2,N3);
        barp(p);
        stage32C(SB2, hb1 + K0h * 64 + 2048, t2); cpa_commit();

        // d1 chunks
        cpa_wait<1>(); barp(p);
        CCHUNK(SA2, 256 + K0h, wr1, wz1, wn1, S0,S1,S2,S3, Y0,Y1,Y2,Y3, M0,M1,M2,M3);
        cpa_wait<0>(); barp(p);
        CCHUNK(SB2, 256 + K0h + 32, wr1, wz1, wn1, S0,S1,S2,S3, Y0,Y1,Y2,Y3, M0,M1,M2,M3);

        __syncthreads();   // all partitions consumed all slots -> red overlay safe

        // publish both dirs' partials
        PUB(0,0,0,R0) PUB(0,0,1,R1) PUB(0,0,2,R2) PUB(0,0,3,R3)
        PUB(0,1,0,Z0) PUB(0,1,1,Z1) PUB(0,1,2,Z2) PUB(0,1,3,Z3)
        PUB(0,2,0,N0) PUB(0,2,1,N1) PUB(0,2,2,N2) PUB(0,2,3,N3)
        PUB(1,0,0,S0) PUB(1,0,1,S1) PUB(1,0,2,S2) PUB(1,0,3,S3)
        PUB(1,1,0,Y0) PUB(1,1,1,Y1) PUB(1,1,2,Y2) PUB(1,1,3,Y3)
        PUB(1,2,0,M0) PUB(1,2,1,M1) PUB(1,2,2,M2) PUB(1,2,3,M3)
        __syncthreads();

        // combined epilogue: one cell per thread (256 d0 + 256 d1)
        float hnew;
        {
            const float* eBase = redF + (size_t)edir * REDD
                               + (eb >> 4) * 80 + (ec * 16 + (eb & 15));
            float Rm = 0.f, Zm = 0.f, Nm = 0.f;
            #pragma unroll
            for (int q = 0; q < 8; ++q) {
                const float* e = eBase + (size_t)q * 960;
                Rm += e[0]; Zm += e[320]; Nm += e[640];
            }
            const float* xgS = (const float*)((char*)smem + WS_BYTES + 131072);
            float xr = xgS[(0*8 + ec + 4*edir) * 64 + eb];
            float xz = xgS[(1*8 + ec + 4*edir) * 64 + eb];
            float xn = xgS[(2*8 + ec + 4*edir) * 64 + eb];
            float rv = sigf(xr + Rm);
            float zv = sigf(xz + Zm);
            float nv = tanf_fast(xn + rv * (Nm + ebh));
            hnew = (1.f - zv) * nv + zv * hprev;
            hprev = hnew;
            hOut[(size_t)ws * 32768] = hnew;
        }

        __threadfence();
        __syncthreads();
        ull tg0 = 0, tg1 = 0;
        if (tid == 0) {
            tg0 = arrive_cnt(&g_cnt[0][0]);
            tg1 = arrive_cnt(&g_cnt[1][0]);
        }
        out[outBase + (size_t)t * (2 * Hh)] = hnew;   // off the sync critical path

        if (t + 1 < Tt) {
            if (tid == 0) {
                poll_cnt(&g_cnt[0][0], tg0);
                poll_cnt(&g_cnt[1][0], tg1);
                asm volatile("fence.acq_rel.gpu;" ::: "memory");
            }
            __syncthreads();
            const float* hb0n = &g_h[0][ws][0][0][0];
            stage32C(SA2, hb0n + K0h * 64, t2);
            if (p == 0) {
                const float4* xs = (const float4*)&g_xg[bid][t + 1][0];
                #pragma unroll
                for (int i = 0; i < 6; ++i)
                    cpa16(xgA + (unsigned)((t2 + i * 64) * 16), xs + t2 + i * 64);
            }
            cpa_commit();
            stage32C(SB2, hb0n + K0h * 64 + 2048, t2);
            cpa_commit();
        }
    }
}

extern "C" void kernel_launch(void* const* d_in, const int* in_sizes, int n_in,
                              void* d_out, int out_size) {
    const float* data  = (const float*)d_in[0];
    const float* Wi_f  = (const float*)d_in[1];
    const float* bi_f  = (const float*)d_in[2];
    const float* Wh_f  = (const float*)d_in[3];
    const float* bhn_f = (const float*)d_in[4];
    const float* Wi_b  = (const float*)d_in[5];
    const float* bi_b  = (const float*)d_in[6];
    const float* Wh_b  = (const float*)d_in[7];
    const float* bhn_b = (const float*)d_in[8];
    float* out = (float*)d_out;

    cudaFuncSetAttribute(gru_persist, cudaFuncAttributeMaxDynamicSharedMemorySize, SMEM_BYTES);

    gru_persist<<<GRIDN, NTHR, SMEM_BYTES>>>(data, Wi_f, bi_f, Wh_f, bhn_f,
                                             Wi_b, bi_b, Wh_b, bhn_b, out);
}

// round 15
// speedup vs baseline: 1.6418x; 1.2985x over previous
#include <cuda_runtime.h>
#include <cstdint>
#include <math.h>

#define Bb 64
#define Tt 512
#define Ff 256
#define Hh 512
#define TFs (Tt*Ff)
#define GRIDN 128
#define NTHR 512
#define WSTRIDE 772
#define WS_BYTES (24*WSTRIDE*4)        // 74112
// phase-1 slots (b-major layout)
#define VROWB 144
#define VSLOTB 9216
// phase-2 slots (kp layout): 16 kp-rows x 512B
#define VSLOTB2 8192
#define SMEM_BYTES (WS_BYTES + 16*VSLOTB)   // 221568 (phase-1 region governs)
#define OST (Tt*2*Hh)

typedef unsigned long long ull;

__device__ float g_h[2][2][Hh/2][Bb][2];   // [dir][slot][kpair][b][parity]
__device__ float g_xg[GRIDN][Tt][1536];    // precomputed x-gates (+bi), per block
__device__ ull   g_barc[32];               // per-direction monotonic counters

// ---------------- helpers ----------------
static __device__ __forceinline__ ull fma2(ull a, ull b, ull c) {
    ull d; asm("fma.rn.f32x2 %0, %1, %2, %3;" : "=l"(d) : "l"(a), "l"(b), "l"(c));
    return d;
}
static __device__ __forceinline__ float lof(ull x) { return __uint_as_float((unsigned)x); }
static __device__ __forceinline__ float hif(ull x) { return __uint_as_float((unsigned)(x >> 32)); }

// volatile is load-bearing (R5/R6 bug: pure asm hoists across barrier asms)
#define LDS128O(base, O, a, b) \
    asm volatile("ld.shared.v2.b64 {%0,%1}, [%2+" #O "];" : "=l"(a), "=l"(b) : "r"(base))
#define LDS64O(base, O, a) \
    asm volatile("ld.shared.b64 %0, [%1+" #O "];" : "=l"(a) : "r"(base))

static __device__ __forceinline__ void cpa16(unsigned s, const float4* g) {
    asm volatile("cp.async.cg.shared.global [%0], [%1], 16;"
                 :: "r"(s), "l"(__cvta_generic_to_global((const void*)g)));
}
static __device__ __forceinline__ void cpa_commit() {
    asm volatile("cp.async.commit_group;");
}
template<int N> static __device__ __forceinline__ void cpa_wait() {
    asm volatile("cp.async.wait_group %0;" :: "n"(N) : "memory");
}

static __device__ __forceinline__ float sigf(float x) {
    return __fdividef(1.f, 1.f + __expf(-x));
}
static __device__ __forceinline__ float tanf_fast(float x) {
    return __fdividef(2.f, 1.f + __expf(-2.f * x)) - 1.f;
}

static __device__ __forceinline__ void barp(int p) {
    asm volatile("bar.sync %0, 64;" :: "r"(p + 1) : "memory");
}

// split barrier primitives on a 64-arrival monotonic counter (graph-replay safe)
static __device__ __forceinline__ ull arrive64(ull* ctr) {
    ull old;
    asm volatile("atom.release.gpu.global.add.u64 %0, [%1], 1;"
                 : "=l"(old) : "l"(ctr) : "memory");
    return (old / 64ULL + 1ULL) * 64ULL;
}
static __device__ __forceinline__ void poll64(ull* ctr, ull tgt) {
    while (true) {
        ull cur;
        asm volatile("ld.acquire.gpu.global.u64 %0, [%1];"
                     : "=l"(cur) : "l"(ctr) : "memory");
        if (cur >= tgt) break;
        __nanosleep(20);
    }
    asm volatile("fence.acq_rel.gpu;" ::: "memory");
}

// full barrier (one-time uses only; conservative fencing)
static __device__ __forceinline__ void grid_barrier(int d) {
    __threadfence();
    __syncthreads();
    if (threadIdx.x == 0) {
        ull tgt = arrive64(&g_barc[d * 16]);
        poll64(&g_barc[d * 16], tgt);
    }
    __syncthreads();
}

// phase-1 stage: 32k x 64b chunk, b-major rows (stride sstr), no commit
static __device__ __forceinline__ void stage32(unsigned dst, const float* sb,
                                               int sstr, int t2) {
#pragma unroll
    for (int j = 0; j < 8; ++j) {
        int idx = t2 + j * 64;
        int b = idx >> 3, f = idx & 7;
        cpa16(dst + (unsigned)(b * VROWB + f * 16),
              (const float4*)(sb + (size_t)b * sstr) + f);
    }
}
// phase-2 stage: contiguous 8KB copy, no commit
static __device__ __forceinline__ void stage32C(unsigned dst, const float* sb, int t2) {
#pragma unroll
    for (int j = 0; j < 8; ++j) {
        int idx = t2 + j * 64;
        cpa16(dst + (unsigned)idx * 16u, (const float4*)sb + idx);
    }
}

// shared fma body (48 fma.f32x2)
#define FMABODY \
  R0=fma2(a0,qa0,R0); R0=fma2(a1,qa1,R0); \
  R1=fma2(e0,qa0,R1); R1=fma2(e1,qa1,R1); \
  R2=fma2(f0,qa0,R2); R2=fma2(f1,qa1,R2); \
  R3=fma2(g0,qa0,R3); R3=fma2(g1,qa1,R3); \
  R4=fma2(a0,qb0,R4); R4=fma2(a1,qb1,R4); \
  R5=fma2(e0,qb0,R5); R5=fma2(e1,qb1,R5); \
  R6=fma2(f0,qb0,R6); R6=fma2(f1,qb1,R6); \
  R7=fma2(g0,qb0,R7); R7=fma2(g1,qb1,R7); \
  Z0=fma2(a0,sa0,Z0); Z0=fma2(a1,sa1,Z0); \
  Z1=fma2(e0,sa0,Z1); Z1=fma2(e1,sa1,Z1); \
  Z2=fma2(f0,sa0,Z2); Z2=fma2(f1,sa1,Z2); \
  Z3=fma2(g0,sa0,Z3); Z3=fma2(g1,sa1,Z3); \
  Z4=fma2(a0,sb0,Z4); Z4=fma2(a1,sb1,Z4); \
  Z5=fma2(e0,sb0,Z5); Z5=fma2(e1,sb1,Z5); \
  Z6=fma2(f0,sb0,Z6); Z6=fma2(f1,sb1,Z6); \
  Z7=fma2(g0,sb0,Z7); Z7=fma2(g1,sb1,Z7); \
  N0=fma2(a0,wa0,N0); N0=fma2(a1,wa1,N0); \
  N1=fma2(e0,wa0,N1); N1=fma2(e1,wa1,N1); \
  N2=fma2(f0,wa0,N2); N2=fma2(f1,wa1,N2); \
  N3=fma2(g0,wa0,N3); N3=fma2(g1,wa1,N3); \
  N4=fma2(a0,wb0,N4); N4=fma2(a1,wb1,N4); \
  N5=fma2(e0,wb0,N5); N5=fma2(e1,wb1,N5); \
  N6=fma2(f0,wb0,N6); N6=fma2(f1,wb1,N6); \
  N7=fma2(g0,wb0,N7); N7=fma2(g1,wb1,N7);

// phase-1 GITER (b-major v layout): 10 LDS.128
#define GITER(O) { \
  ull a0,a1,e0,e1,f0,f1,g0,g1; \
  ull qa0,qa1,qb0,qb1, sa0,sa1,sb0,sb1, wa0,wa1,wb0,wb1; \
  LDS128O(va0,O,a0,a1); LDS128O(va1,O,e0,e1); \
  LDS128O(va2,O,f0,f1); LDS128O(va3,O,g0,g1); \
  LDS128O(xr0,O,qa0,qa1); LDS128O(xr1,O,qb0,qb1); \
  LDS128O(xz0,O,sa0,sa1); LDS128O(xz1,O,sb0,sb1); \
  LDS128O(xn0,O,wa0,wa1); LDS128O(xn1,O,wb0,wb1); \
  FMABODY }

#define COMPUTE_CHUNK(SLOT, KK) { \
  const unsigned va0 = (SLOT) + vb0, va1 = (SLOT) + vb1, \
                 va2 = (SLOT) + vb2, va3 = (SLOT) + vb3; \
  const unsigned xr0 = wr0 + (unsigned)(KK)*4u, xr1 = wr1 + (unsigned)(KK)*4u; \
  const unsigned xz0 = wz0 + (unsigned)(KK)*4u, xz1 = wz1 + (unsigned)(KK)*4u; \
  const unsigned xn0 = wn0 + (unsigned)(KK)*4u, xn1 = wn1 + (unsigned)(KK)*4u; \
  GITER(0)  GITER(16) GITER(32) GITER(48) \
  GITER(64) GITER(80) GITER(96) GITER(112) }

// phase-2 GITER (kp-major v layout): 8 LDS.64 (1 wf each) + 6 LDS.128 (broadcast)
#define GITER2(OV0, OV1, OW) { \
  ull a0,a1,e0,e1,f0,f1,g0,g1; \
  ull qa0,qa1,qb0,qb1, sa0,sa1,sb0,sb1, wa0,wa1,wb0,wb1; \
  LDS64O(ua0,OV0,a0); LDS64O(ua0,OV1,a1); \
  LDS64O(ua1,OV0,e0); LDS64O(ua1,OV1,e1); \
  LDS64O(ua2,OV0,f0); LDS64O(ua2,OV1,f1); \
  LDS64O(ua3,OV0,g0); LDS64O(ua3,OV1,g1); \
  LDS128O(xr0,OW,qa0,qa1); LDS128O(xr1,OW,qb0,qb1); \
  LDS128O(xz0,OW,sa0,sa1); LDS128O(xz1,OW,sb0,sb1); \
  LDS128O(xn0,OW,wa0,wa1); LDS128O(xn1,OW,wb0,wb1); \
  FMABODY }

#define COMPUTE_CHUNK2(SLOT, KK) { \
  const unsigned ua0 = (SLOT) + (unsigned)(bb*8), ua1 = ua0 + 128u, \
                 ua2 = ua0 + 256u, ua3 = ua0 + 384u; \
  const unsigned xr0 = wr0 + (unsigned)(KK)*4u, xr1 = wr1 + (unsigned)(KK)*4u; \
  const unsigned xz0 = wz0 + (unsigned)(KK)*4u, xz1 = wz1 + (unsigned)(KK)*4u; \
  const unsigned xn0 = wn0 + (unsigned)(KK)*4u, xn1 = wn1 + (unsigned)(KK)*4u; \
  GITER2(0,512,0)       GITER2(1024,1536,16) \
  GITER2(2048,2560,32)  GITER2(3072,3584,48) \
  GITER2(4096,4608,64)  GITER2(5120,5632,80) \
  GITER2(6144,6656,96)  GITER2(7168,7680,112) }

#define P1ST(ACC, GA, CG, G, BI) \
  xgrow[((GA)*8 + cg4 + 4*(CG))*64 + bb + 16*(G)] = lof(ACC) + hif(ACC) + (BI);

#define PUB(GA, M, ACC) rp[(GA)*512 + (M)*64 + t2] = lof(ACC) + hif(ACC);

// ---------------- persistent fused BiGRU ----------------
extern "C" __global__ void __launch_bounds__(NTHR, 1)
gru_persist(const float* __restrict__ data,
            const float* __restrict__ Wi_f, const float* __restrict__ bi_f,
            const float* __restrict__ Wh_f, const float* __restrict__ bhn_f,
            const float* __restrict__ Wi_b, const float* __restrict__ bi_b,
            const float* __restrict__ Wh_b, const float* __restrict__ bhn_b,
            float* __restrict__ out) {
    extern __shared__ float smem[];
    float* Ws   = smem;                                  // [24][772]
    float* redF = (float*)((char*)smem + WS_BYTES);      // overlays phase-2 slots

    const int tid = threadIdx.x;
    const int bid = blockIdx.x;
    const int d   = bid >> 6;
    const int cb  = (bid & 63) * 8;

    const float* Wi  = d ? Wi_b  : Wi_f;
    const float* Wh  = d ? Wh_b  : Wh_f;
    const float* bi  = d ? bi_b  : bi_f;
    const float* bhn = d ? bhn_b : bhn_f;

    for (int idx = tid; idx < 24 * 768; idx += NTHR) {
        int k = idx / 24, j = idx - k * 24;
        int g = j >> 3, cc = j & 7;
        int gcol = g * Hh + cb + cc;
        Ws[j * WSTRIDE + k] = (k < Ff) ? Wi[(size_t)k * (3 * Hh) + gcol]
                                       : Wh[(size_t)(k - Ff) * (3 * Hh) + gcol];
    }
    // zero my 8 h-columns of slot 0 (contiguous 512 floats in kp layout)
    ((float*)&g_h[d][0][cb >> 1][0][0])[tid] = 0.f;

    const int p   = tid >> 6;
    const int t2  = tid & 63;
    const int bb  = t2 & 15;
    const int cg4 = t2 >> 4;

    // epilogue cell mapping (cell m = tid); hprev carried in a register
    const int eM  = tid >> 6, et2 = tid & 63;
    const int ebq = (et2 & 15) + 16 * (eM & 3);
    const int ecc = (et2 >> 4) + 4 * (eM >> 2);
    const float ebh = bhn[cb + ecc];
    float* hSlot = &g_h[d][0][(cb + ecc) >> 1][ebq][ecc & 1];   // + ws*32768 floats
    const size_t outB = (size_t)ebq * OST + (size_t)d * Hh + cb + ecc;

    const float bi00 = bi[cb + cg4],        bi01 = bi[cb + cg4 + 4];
    const float bi10 = bi[Hh + cb + cg4],   bi11 = bi[Hh + cb + cg4 + 4];
    const float bi20 = bi[2*Hh + cb + cg4], bi21 = bi[2*Hh + cb + cg4 + 4];

    const unsigned wsA = (unsigned)__cvta_generic_to_shared(Ws);
    const unsigned vsA = (unsigned)__cvta_generic_to_shared((char*)smem + WS_BYTES);
    const unsigned xgA = vsA + 131072u;    // after 16 phase-2 slots
    const unsigned vb0 = (unsigned)(bb        * VROWB);
    const unsigned vb1 = (unsigned)((bb + 16) * VROWB);
    const unsigned vb2 = (unsigned)((bb + 32) * VROWB);
    const unsigned vb3 = (unsigned)((bb + 48) * VROWB);
    const unsigned wr0 = wsA + (unsigned)((0  + cg4)     * WSTRIDE) * 4u;
    const unsigned wr1 = wsA + (unsigned)((0  + cg4 + 4) * WSTRIDE) * 4u;
    const unsigned wz0 = wsA + (unsigned)((8  + cg4)     * WSTRIDE) * 4u;
    const unsigned wz1 = wsA + (unsigned)((8  + cg4 + 4) * WSTRIDE) * 4u;
    const unsigned wn0 = wsA + (unsigned)((16 + cg4)     * WSTRIDE) * 4u;
    const unsigned wn1 = wsA + (unsigned)((16 + cg4 + 4) * WSTRIDE) * 4u;

    // ===== PHASE 1: xg = x@Wi + bi (b-major slots; partition p owns t = 8j+p) =====
    {
        const unsigned SA = vsA + (unsigned)(2 * p)     * VSLOTB;
        const unsigned SB = vsA + (unsigned)(2 * p + 1) * VSLOTB;
        stage32(SA, data + (size_t)p * Ff,      TFs, t2); cpa_commit();
        stage32(SB, data + (size_t)p * Ff + 32, TFs, t2); cpa_commit();

        for (int jt = 0; jt < 64; ++jt) {
            const int t = 8 * jt + p;
            ull R0=0,R1=0,R2=0,R3=0,R4=0,R5=0,R6=0,R7=0;
            ull Z0=0,Z1=0,Z2=0,Z3=0,Z4=0,Z5=0,Z6=0,Z7=0;
            ull N0=0,N1=0,N2=0,N3=0,N4=0,N5=0,N6=0,N7=0;

            #pragma unroll 1
            for (int j = 0; j < 8; ++j) {
                if (jt == 63 && j == 7) { cpa_wait<0>(); } else { cpa_wait<1>(); }
                barp(p);
                COMPUTE_CHUNK((j & 1) ? SB : SA, 32 * j);
                barp(p);
                if (jt < 63 || j < 6) {
                    const int tS = (j < 6) ? t : t + 8;
                    const int kS = ((j + 2) & 7) * 32;
                    stage32((j & 1) ? SB : SA, data + (size_t)tS * Ff + kS, TFs, t2);
                    cpa_commit();
                }
            }

            float* xgrow = &g_xg[bid][t][0];
            P1ST(R0,0,0,0,bi00) P1ST(R1,0,0,1,bi00) P1ST(R2,0,0,2,bi00) P1ST(R3,0,0,3,bi00)
            P1ST(R4,0,1,0,bi01) P1ST(R5,0,1,1,bi01) P1ST(R6,0,1,2,bi01) P1ST(R7,0,1,3,bi01)
            P1ST(Z0,1,0,0,bi10) P1ST(Z1,1,0,1,bi10) P1ST(Z2,1,0,2,bi10) P1ST(Z3,1,0,3,bi10)
            P1ST(Z4,1,1,0,bi11) P1ST(Z5,1,1,1,bi11) P1ST(Z6,1,1,2,bi11) P1ST(Z7,1,1,3,bi11)
            P1ST(N0,2,0,0,bi20) P1ST(N1,2,0,1,bi20) P1ST(N2,2,0,2,bi20) P1ST(N3,2,0,3,bi20)
            P1ST(N4,2,1,0,bi21) P1ST(N5,2,1,1,bi21) P1ST(N6,2,1,2,bi21) P1ST(N7,2,1,3,bi21)
        }
    }

    grid_barrier(d);   // xg + h zeros + weights visible chip-wide (one-time)

    // ===== PHASE 2: recurrence (kp-layout slots; partition p: 16KB at p*16384) =====
    const unsigned SA2 = vsA + (unsigned)p * 16384u;
    const unsigned SB2 = SA2 + (unsigned)VSLOTB2;
    const int K0h = p * 64;
    float hprev = 0.f;

    {
        const float* hb = &g_h[d][0][0][0][0];
        stage32C(SA2, hb + K0h * 64, t2);
        if (p == 0) {
            const float4* xs = (const float4*)&g_xg[bid][0][0];
            #pragma unroll
            for (int i = 0; i < 6; ++i)
                cpa16(xgA + (unsigned)((t2 + i * 64) * 16), xs + t2 + i * 64);
        }
        cpa_commit();
        stage32C(SB2, hb + K0h * 64 + 2048, t2);
        cpa_commit();
    }

    for (int t = 0; t < Tt; ++t) {
        const int ws = (t + 1) & 1;

        ull R0=0,R1=0,R2=0,R3=0,R4=0,R5=0,R6=0,R7=0;
        ull Z0=0,Z1=0,Z2=0,Z3=0,Z4=0,Z5=0,Z6=0,Z7=0;
        ull N0=0,N1=0,N2=0,N3=0,N4=0,N5=0,N6=0,N7=0;

        cpa_wait<1>(); barp(p);
        COMPUTE_CHUNK2(SA2, 256 + K0h);
        cpa_wait<0>(); barp(p);
        COMPUTE_CHUNK2(SB2, 256 + K0h + 32);
        barp(p);   // partition done reading its slots (+compiler fence)

        {   // publish f32 partials into OWN slot region (16KB stride)
            float* rp = redF + (size_t)p * 4096;
            PUB(0,0,R0) PUB(0,1,R1) PUB(0,2,R2) PUB(0,3,R3)
            PUB(0,4,R4) PUB(0,5,R5) PUB(0,6,R6) PUB(0,7,R7)
            PUB(1,0,Z0) PUB(1,1,Z1) PUB(1,2,Z2) PUB(1,3,Z3)
            PUB(1,4,Z4) PUB(1,5,Z5) PUB(1,6,Z6) PUB(1,7,Z7)
            PUB(2,0,N0) PUB(2,1,N1) PUB(2,2,N2) PUB(2,3,N3)
            PUB(2,4,N4) PUB(2,5,N5) PUB(2,6,N6) PUB(2,7,N7)
        }
        __syncthreads();

        float hnew;
        {   // distributed epilogue: thread finalizes cell m = tid (hprev in reg)
            float Rm = 0.f, Zm = 0.f, Nm = 0.f;
            #pragma unroll
            for (int q = 0; q < 8; ++q) {
                const float* e = redF + (size_t)q * 4096;
                Rm += e[tid]; Zm += e[512 + tid]; Nm += e[1024 + tid];
            }
            const float* xgS = (const float*)((char*)smem + WS_BYTES + 131072);
            float xr = xgS[(0*8 + ecc) * 64 + ebq];
            float xz = xgS[(1*8 + ecc) * 64 + ebq];
            float xn = xgS[(2*8 + ecc) * 64 + ebq];
            float rv = sigf(xr + Rm);
            float zv = sigf(xz + Zm);
            float nv = tanf_fast(xn + rv * (Nm + ebh));
            hnew = (1.f - zv) * nv + zv * hprev;
            hprev = hnew;
            hSlot[(size_t)ws * 32768] = hnew;   // g_h slot stride = 32768 floats
        }

        // split barrier: all h stores done -> tid0 arrives; out store off-path; poll
        __syncthreads();
        ull tg = 0;
        if (tid == 0) tg = arrive64(&g_barc[d * 16]);
        out[outB + (size_t)t * (2 * Hh)] = hnew;
        if (tid == 0) poll64(&g_barc[d * 16], tg);
        __syncthreads();

        if (t + 1 < Tt) {
            const float* hb = &g_h[d][ws][0][0][0];
            stage32C(SA2, hb + K0h * 64, t2);
            if (p == 0) {
                const float4* xs = (const float4*)&g_xg[bid][t + 1][0];
                #pragma unroll
                for (int i = 0; i < 6; ++i)
                    cpa16(xgA + (unsigned)((t2 + i * 64) * 16), xs + t2 + i * 64);
            }
            cpa_commit();
            stage32C(SB2, hb + K0h * 64 + 2048, t2);
            cpa_commit();
        }
    }
}

extern "C" void kernel_launch(void* const* d_in, const int* in_sizes, int n_in,
                              void* d_out, int out_size) {
    const float* data  = (const float*)d_in[0];
    const float* Wi_f  = (const float*)d_in[1];
    const float* bi_f  = (const float*)d_in[2];
    const float* Wh_f  = (const float*)d_in[3];
    const float* bhn_f = (const float*)d_in[4];
    const float* Wi_b  = (const float*)d_in[5];
    const float* bi_b  = (const float*)d_in[6];
    const float* Wh_b  = (const float*)d_in[7];
    const float* bhn_b = (const float*)d_in[8];
    float* out = (float*)d_out;

    cudaFuncSetAttribute(gru_persist, cudaFuncAttributeMaxDynamicSharedMemorySize, SMEM_BYTES);

    gru_persist<<<GRIDN, NTHR, SMEM_BYTES>>>(data, Wi_f, bi_f, Wh_f, bhn_f,
                                             Wi_b, bi_b, Wh_b, bhn_b, out);
}